// round 3
// baseline (speedup 1.0000x reference)
#include <cuda_runtime.h>
#include <cuda_bf16.h>
#include <cstdint>

typedef unsigned long long u64;

// Problem: b=4, h=8, L=8192, dk=dv=64, chunk=32. 32 chains x 256 chunks.
#define G_CHUNKS 8192
#define O_ELEMS  16777216   // 4*8*8192*64

// ---------------- scratch (device globals; allocation-free rule) -----------
__device__ float4 g_qn4[G_CHUNKS * 512];   // qn  [g][32][64] row-major
__device__ float4 g_w4 [G_CHUNKS * 512];   // -w  [g][32][64] row-major (NEGATED)
__device__ float4 g_kT4[G_CHUNKS * 512];   // k^T [g][64][32]
__device__ float4 g_uT4[G_CHUNKS * 512];   // u^T [g][64][32]
__device__ float4 g_Lc4[G_CHUNKS * 256];   // Lc  [g][32][32] (tril incl diag, rest 0)

// ---------------- f32x2 / LDS helpers --------------------------------------
__device__ __forceinline__ u64 fma2(u64 a, u64 b, u64 c) {
    u64 d; asm("fma.rn.f32x2 %0, %1, %2, %3;" : "=l"(d) : "l"(a), "l"(b), "l"(c)); return d;
}
__device__ __forceinline__ u64 mul2(u64 a, u64 b) {
    u64 d; asm("mul.rn.f32x2 %0, %1, %2;" : "=l"(d) : "l"(a), "l"(b)); return d;
}
__device__ __forceinline__ u64 pack2(float x, float y) {
    u64 d; asm("mov.b64 %0, {%1, %2};" : "=l"(d) : "f"(x), "f"(y)); return d;
}
__device__ __forceinline__ float2 unpack2(u64 a) {
    float2 r; asm("mov.b64 {%0, %1}, %2;" : "=f"(r.x), "=f"(r.y) : "l"(a)); return r;
}
__device__ __forceinline__ void ldsv2(u64& a, u64& b, uint32_t addr) {
    asm volatile("ld.shared.v2.u64 {%0, %1}, [%2];" : "=l"(a), "=l"(b) : "r"(addr));
}
__device__ __forceinline__ void sts_dup(uint32_t addr, float v) {
    asm volatile("st.shared.v2.f32 [%0], {%1, %1};" :: "r"(addr), "f"(v));
}
__device__ __forceinline__ void sts_u64(uint32_t addr, u64 v) {
    asm volatile("st.shared.b64 [%0], %1;" :: "r"(addr), "l"(v));
}
__device__ __forceinline__ uint32_t s2u(const void* p) {
    return (uint32_t)__cvta_generic_to_shared(p);
}

// ===========================================================================
// Phase 1: per-chunk preprocessing. One 256-thread block per chunk.
// ===========================================================================
__global__ void __launch_bounds__(256) dn_phase1(
    const float* __restrict__ q, const float* __restrict__ k,
    const float* __restrict__ v, const float* __restrict__ beta)
{
    __shared__ float sQ[32 * 68], sK[32 * 68], sV[32 * 68];  // stride 68 (16B align)
    __shared__ float sA[32 * 33];
    __shared__ float sRinv[64], sBeta[32];

    const int tid  = threadIdx.x;
    const int lane = tid & 31;
    const int wp   = tid >> 5;
    const size_t g = blockIdx.x;

    const uint32_t aQ = s2u(sQ), aK = s2u(sK), aV = s2u(sV);

    // ---- load q,k,v chunk (32x64) as float4 into stride-68 smem -------------
    const float4* qb = (const float4*)(q + g * 2048);
    const float4* kb = (const float4*)(k + g * 2048);
    const float4* vb = (const float4*)(v + g * 2048);
#pragma unroll
    for (int it = 0; it < 2; ++it) {
        int f  = tid + it * 256;
        int so = (f >> 4) * 68 + ((f & 15) << 2);
        *(float4*)&sQ[so] = qb[f];
        *(float4*)&sK[so] = kb[f];
        *(float4*)&sV[so] = vb[f];
    }
    if (tid < 32) sBeta[tid] = beta[g * 32 + tid];
    __syncthreads();

    // ---- l2-norm rsqrt factors (vectorized) ----------------------------------
    if (tid < 64) {
        const float4* rp = (const float4*)((tid < 32) ? (sQ + tid * 68) : (sK + (tid - 32) * 68));
        float s = 1e-6f;
#pragma unroll
        for (int m = 0; m < 16; ++m) {
            float4 a = rp[m];
            s = fmaf(a.x, a.x, s); s = fmaf(a.y, a.y, s);
            s = fmaf(a.z, a.z, s); s = fmaf(a.w, a.w, s);
        }
        sRinv[tid] = rsqrtf(s);
    }
    __syncthreads();
    for (int e = tid; e < 2048; e += 256) {
        int r = e >> 6, d = e & 63;
        sQ[r * 68 + d] *= sRinv[r];
        sK[r * 68 + d] *= sRinv[32 + r];
    }
    __syncthreads();

    // ---- A (strict lower, -beta_i kn_i.kn_j) and Lc = tril(qn kn^T) ----------
    {
        const int i0 = wp * 4;
        u64 a2A[4] = {0, 0, 0, 0}, a2L[4] = {0, 0, 0, 0};
#pragma unroll 4
        for (int dd = 0; dd < 16; ++dd) {          // 4 d's per iter
            u64 kj0, kj1;
            ldsv2(kj0, kj1, aK + (uint32_t)(lane * 272 + dd * 16));
#pragma unroll
            for (int e = 0; e < 4; ++e) {
                u64 ki0, ki1, qi0, qi1;
                ldsv2(ki0, ki1, aK + (uint32_t)((i0 + e) * 272 + dd * 16));   // broadcast
                ldsv2(qi0, qi1, aQ + (uint32_t)((i0 + e) * 272 + dd * 16));   // broadcast
                a2A[e] = fma2(ki0, kj0, a2A[e]);  a2A[e] = fma2(ki1, kj1, a2A[e]);
                a2L[e] = fma2(qi0, kj0, a2L[e]);  a2L[e] = fma2(qi1, kj1, a2L[e]);
            }
        }
        float* g_Lc = (float*)g_Lc4 + g * 1024;
#pragma unroll
        for (int e = 0; e < 4; ++e) {
            int i = i0 + e;
            float2 ra = unpack2(a2A[e]);
            float2 rl = unpack2(a2L[e]);
            float accA = ra.x + ra.y, accL = rl.x + rl.y;
            sA[i * 33 + lane]   = (lane <  i) ? (-sBeta[i] * accA) : 0.0f;
            g_Lc[i * 32 + lane] = (lane <= i) ? accL : 0.0f;
        }
    }
    __syncthreads();

    // ---- forward substitution: sA -> T = (I-A)^{-1} - I (strict lower) -------
    if (wp == 0) {
        for (int i = 1; i < 32; ++i) {
            float r   = sA[i * 33 + lane];
            float val = r;
            for (int j = 1; j < i; ++j) {
                float aij = __shfl_sync(0xffffffffu, r, j);
                if (lane < j) val = fmaf(aij, sA[j * 33 + lane], val);
            }
            sA[i * 33 + lane] = val;
            __syncwarp();
        }
    }
    __syncthreads();

    // ---- fold beta into T columns --------------------------------------------
    for (int e = tid; e < 1024; e += 256) {
        int i = e >> 5, j = e & 31;
        sA[i * 33 + j] *= sBeta[j];
    }
    __syncthreads();

    // ---- u = M @ (beta v), w = M @ (beta kn); store uT and NEGATED w ----------
#pragma unroll
    for (int p = 0; p < 4; ++p) {
        const bool isU = (p < 2);
        const int dcb  = p * 32 + wp * 4;
        const int db   = isU ? dcb : (dcb - 64);
        const uint32_t aX = isU ? aV : aK;
        float bi = sBeta[lane];
        u64 b2 = pack2(bi, bi);
        u64 x01, x23;
        ldsv2(x01, x23, aX + (uint32_t)(lane * 272 + db * 4));
        u64 a01 = mul2(b2, x01), a23 = mul2(b2, x23);
#pragma unroll 8
        for (int j = 0; j < 32; ++j) {
            float t = sA[lane * 33 + j];                 // zero for j >= lane
            u64 t2 = pack2(t, t);
            ldsv2(x01, x23, aX + (uint32_t)(j * 272 + db * 4));  // broadcast
            a01 = fma2(t2, x01, a01);
            a23 = fma2(t2, x23, a23);
        }
        float2 r01 = unpack2(a01), r23 = unpack2(a23);
        if (isU) {
            float* uT = (float*)g_uT4 + g * 2048;
            uT[(db + 0) * 32 + lane] = r01.x;
            uT[(db + 1) * 32 + lane] = r01.y;
            uT[(db + 2) * 32 + lane] = r23.x;
            uT[(db + 3) * 32 + lane] = r23.y;
        } else {
            g_w4[g * 512 + lane * 16 + (db >> 2)] = make_float4(-r01.x, -r01.y, -r23.x, -r23.y);
        }
    }

    // ---- store qn row-major, kT [d][i] ---------------------------------------
    {
        float* g_qn = (float*)g_qn4 + g * 2048;
        float* g_kT = (float*)g_kT4 + g * 2048;
        for (int e = tid; e < 2048; e += 256) {
            int r = e >> 6, d = e & 63;
            g_qn[e] = sQ[r * 68 + d];
        }
        for (int f = tid; f < 2048; f += 256) {
            int d = f >> 5, i = f & 31;
            g_kT[f] = sK[i * 68 + d];
        }
    }
}

// ===========================================================================
// Phase 2: sequential scan. 128 blocks = 32 chains x 4 dv-splits (16 cols).
// Warp wp owns dv cols c0=split*16+wp*2, c0+1 as f32x2 pairs.
// Staging smem holds DUPLICATED (x,x) pairs so every fma2 multiplier is
// load-formed. Double-buffered: one __syncthreads per chunk.
// ===========================================================================
// byte layout per buffer (offsets):
//   QD (qdup 32 rows x 132 floats) : 0       size 16896
//   WD (wdup, negated)             : 16896   size 16896
//   KT (ktdup 64 rows x 76 floats) : 33792   size 19456
//   LC (lcdup 32 rows x 68 floats) : 53248   size  8704
#define P2_BUF   61952
#define P2_QD    0
#define P2_WD    16896
#define P2_KT    33792
#define P2_LC    53248
#define P2_MS    123904           // mirror: 8 warps x 136 floats
#define P2_SMEM  128256

__global__ void __launch_bounds__(256) dn_phase2(float* __restrict__ out, int wantS)
{
    extern __shared__ float smem[];
    const uint32_t sb = s2u(smem);

    const int tid  = threadIdx.x;
    const int lane = tid & 31;
    const int wp   = tid >> 5;
    const int bh   = blockIdx.x >> 2;
    const int c0   = (blockIdx.x & 3) * 16 + wp * 2;
    const uint32_t msb = sb + P2_MS + (uint32_t)wp * 544;

    // zero S mirror (pairs at byte d*8)
    sts_u64(msb + (uint32_t)lane * 8, 0ull);
    sts_u64(msb + (uint32_t)(lane + 32) * 8, 0ull);
    u64 Sa = 0ull, Sb = 0ull;

    const size_t gbase = (size_t)bh * 256;

    float4 rq0, rq1, rw0, rw1, rt0, rt1, rl;
    float  ru0, ru1, cu0, cu1;

#define LOAD_REGS(T) do {                                                      \
    size_t g_ = gbase + (size_t)(T);                                           \
    rq0 = g_qn4[g_ * 512 + tid]; rq1 = g_qn4[g_ * 512 + tid + 256];            \
    rw0 = g_w4 [g_ * 512 + tid]; rw1 = g_w4 [g_ * 512 + tid + 256];            \
    rt0 = g_kT4[g_ * 512 + tid]; rt1 = g_kT4[g_ * 512 + tid + 256];            \
    rl  = g_Lc4[g_ * 256 + tid];                                               \
    ru0 = ((const float*)g_uT4)[g_ * 2048 + (size_t)c0 * 32 + lane];           \
    ru1 = ((const float*)g_uT4)[g_ * 2048 + (size_t)(c0 + 1) * 32 + lane];     \
} while (0)

#define STORE_SMEM(BUF) do {                                                   \
    uint32_t bb = sb + (uint32_t)(BUF) * P2_BUF;                               \
    int row = tid >> 4, db = (tid & 15) << 2;                                  \
    uint32_t qa = bb + P2_QD + (uint32_t)(row * 528 + db * 8);                 \
    sts_dup(qa, rq0.x); sts_dup(qa + 8, rq0.y);                                \
    sts_dup(qa + 16, rq0.z); sts_dup(qa + 24, rq0.w);                          \
    uint32_t qa2 = qa + 16 * 528;                                              \
    sts_dup(qa2, rq1.x); sts_dup(qa2 + 8, rq1.y);                              \
    sts_dup(qa2 + 16, rq1.z); sts_dup(qa2 + 24, rq1.w);                        \
    uint32_t wa = bb + P2_WD + (uint32_t)(row * 528 + db * 8);                 \
    sts_dup(wa, rw0.x); sts_dup(wa + 8, rw0.y);                                \
    sts_dup(wa + 16, rw0.z); sts_dup(wa + 24, rw0.w);                          \
    uint32_t wa2 = wa + 16 * 528;                                              \
    sts_dup(wa2, rw1.x); sts_dup(wa2 + 8, rw1.y);                              \
    sts_dup(wa2 + 16, rw1.z); sts_dup(wa2 + 24, rw1.w);                        \
    int kd = tid >> 3, ib = (tid & 7) << 2;                                    \
    uint32_t ka = bb + P2_KT + (uint32_t)(kd * 304 + ib * 8);                  \
    sts_dup(ka, rt0.x); sts_dup(ka + 8, rt0.y);                                \
    sts_dup(ka + 16, rt0.z); sts_dup(ka + 24, rt0.w);                          \
    uint32_t ka2 = ka + 32 * 304;                                              \
    sts_dup(ka2, rt1.x); sts_dup(ka2 + 8, rt1.y);                              \
    sts_dup(ka2 + 16, rt1.z); sts_dup(ka2 + 24, rt1.w);                        \
    int lr = tid >> 3, jb = (tid & 7) << 2;                                    \
    uint32_t la = bb + P2_LC + (uint32_t)(lr * 272 + jb * 8);                  \
    sts_dup(la, rl.x); sts_dup(la + 8, rl.y);                                  \
    sts_dup(la + 16, rl.z); sts_dup(la + 24, rl.w);                            \
} while (0)

    LOAD_REGS(0);
    STORE_SMEM(0);
    cu0 = ru0; cu1 = ru1;
    __syncthreads();

    for (int t = 0; t < 256; ++t) {
        const uint32_t bb = sb + (uint32_t)(t & 1) * P2_BUF;

        u64 u01 = pack2(cu0, cu1);
        u64 o01 = 0ull;

        if (t + 1 < 256) LOAD_REGS(t + 1);    // LDG overlaps compute

        // ---- u = u0 + (-w)@S ; o = q@S  (S pairs broadcast from mirror) ------
        const uint32_t qrow = bb + P2_QD + (uint32_t)lane * 528;
        const uint32_t wrow = bb + P2_WD + (uint32_t)lane * 528;
#pragma unroll
        for (int i = 0; i < 32; ++i) {        // 2 d's per iter
            u64 w0, w1, q0, q1, s0, s1;
            ldsv2(w0, w1, wrow + (uint32_t)i * 16);
            ldsv2(q0, q1, qrow + (uint32_t)i * 16);
            ldsv2(s0, s1, msb  + (uint32_t)i * 16);
            u01 = fma2(w0, s0, u01);  u01 = fma2(w1, s1, u01);
            o01 = fma2(q0, s0, o01);  o01 = fma2(q1, s1, o01);
        }
        float2 uu = unpack2(u01);

        // ---- o += Lc@u ; S += k^T @ u ----------------------------------------
        const uint32_t lrow  = bb + P2_LC + (uint32_t)lane * 272;
        const uint32_t krow0 = bb + P2_KT + (uint32_t)lane * 304;
        const uint32_t krow1 = bb + P2_KT + (uint32_t)(lane + 32) * 304;
#pragma unroll
        for (int j2 = 0; j2 < 16; ++j2) {     // 2 j's per iter
            u64 l0, l1, ka0, kb0, ka1, kb1;
            ldsv2(l0, l1, lrow  + (uint32_t)j2 * 16);
            ldsv2(ka0, kb0, krow0 + (uint32_t)j2 * 16);
            ldsv2(ka1, kb1, krow1 + (uint32_t)j2 * 16);
            int j = j2 * 2;
            u64 uja = pack2(__shfl_sync(0xffffffffu, uu.x, j),
                            __shfl_sync(0xffffffffu, uu.y, j));
            u64 ujb = pack2(__shfl_sync(0xffffffffu, uu.x, j + 1),
                            __shfl_sync(0xffffffffu, uu.y, j + 1));
            o01 = fma2(l0, uja, o01);  o01 = fma2(l1, ujb, o01);
            Sa  = fma2(ka0, uja, Sa);  Sa  = fma2(kb0, ujb, Sa);
            Sb  = fma2(ka1, uja, Sb);  Sb  = fma2(kb1, ujb, Sb);
        }

        __syncwarp();                          // lanes done reading mirror
        sts_u64(msb + (uint32_t)lane * 8, Sa);
        sts_u64(msb + (uint32_t)(lane + 32) * 8, Sb);

        float2 oo = unpack2(o01);
        size_t orow = ((size_t)bh * 8192 + (size_t)t * 32 + lane) * 64 + c0;
        *(float2*)(out + orow) = oo;

        if (t + 1 < 256) {
            STORE_SMEM((t + 1) & 1);           // fill other buffer, no wait
            cu0 = ru0; cu1 = ru1;
        }
        __syncthreads();                       // buffer (t+1)&1 ready for all
    }

    if (wantS) {
        size_t so = (size_t)O_ELEMS + (size_t)bh * 4096 + (size_t)lane * 64 + c0;
        *(float2*)(out + so)        = unpack2(Sa);
        *(float2*)(out + so + 2048) = unpack2(Sb);   // d = lane+32
    }
#undef LOAD_REGS
#undef STORE_SMEM
}

// ===========================================================================
extern "C" void kernel_launch(void* const* d_in, const int* in_sizes, int n_in,
                              void* d_out, int out_size)
{
    const float* q    = (const float*)d_in[0];
    const float* k    = (const float*)d_in[1];
    const float* v    = (const float*)d_in[2];
    const float* beta = (const float*)d_in[3];
    float* out = (float*)d_out;
    int wantS = (out_size > O_ELEMS) ? 1 : 0;

    cudaFuncSetAttribute(dn_phase2, cudaFuncAttributeMaxDynamicSharedMemorySize, P2_SMEM);

    dn_phase1<<<G_CHUNKS, 256>>>(q, k, v, beta);
    dn_phase2<<<128, 256, P2_SMEM>>>(out, wantS);
}

// round 4
// speedup vs baseline: 1.2927x; 1.2927x over previous
#include <cuda_runtime.h>
#include <cuda_bf16.h>
#include <cstdint>

typedef unsigned long long u64;

// Problem: b=4, h=8, L=8192, dk=dv=64, chunk=32. 32 chains x 256 chunks.
#define G_CHUNKS 8192
#define O_ELEMS  16777216   // 4*8*8192*64

// ---------------- scratch (device globals; allocation-free rule) -----------
__device__ float4 g_qn4[G_CHUNKS * 512];   // qn  [g][32][64] row-major
__device__ float4 g_w4 [G_CHUNKS * 512];   // -w  [g][32][64] row-major (NEGATED)
__device__ float4 g_kT4[G_CHUNKS * 512];   // k^T [g][64][32]
__device__ float4 g_uP4[G_CHUNKS * 512];   // u pairs [g][32 cpair][32 i][2]
__device__ float4 g_Lc4[G_CHUNKS * 256];   // Lc  [g][32][32] (tril incl diag)

// ---------------- f32x2 / LDS helpers --------------------------------------
__device__ __forceinline__ u64 fma2(u64 a, u64 b, u64 c) {
    u64 d; asm("fma.rn.f32x2 %0, %1, %2, %3;" : "=l"(d) : "l"(a), "l"(b), "l"(c)); return d;
}
__device__ __forceinline__ u64 mul2(u64 a, u64 b) {
    u64 d; asm("mul.rn.f32x2 %0, %1, %2;" : "=l"(d) : "l"(a), "l"(b)); return d;
}
__device__ __forceinline__ u64 pack2(float x, float y) {
    u64 d; asm("mov.b64 %0, {%1, %2};" : "=l"(d) : "f"(x), "f"(y)); return d;
}
__device__ __forceinline__ float2 unpack2(u64 a) {
    float2 r; asm("mov.b64 {%0, %1}, %2;" : "=f"(r.x), "=f"(r.y) : "l"(a)); return r;
}
__device__ __forceinline__ float hadd2(u64 a) {
    float2 r = unpack2(a); return r.x + r.y;
}
__device__ __forceinline__ void ldsv2(u64& a, u64& b, uint32_t addr) {
    asm volatile("ld.shared.v2.u64 {%0, %1}, [%2];" : "=l"(a), "=l"(b) : "r"(addr));
}
__device__ __forceinline__ void sts_f32(uint32_t addr, float v) {
    asm volatile("st.shared.f32 [%0], %1;" :: "r"(addr), "f"(v));
}
__device__ __forceinline__ void sts_v4(uint32_t addr, float4 v) {
    asm volatile("st.shared.v4.f32 [%0], {%1,%2,%3,%4};"
                 :: "r"(addr), "f"(v.x), "f"(v.y), "f"(v.z), "f"(v.w));
}
__device__ __forceinline__ uint32_t s2u(const void* p) {
    return (uint32_t)__cvta_generic_to_shared(p);
}

// ===========================================================================
// Phase 1: per-chunk preprocessing. One 256-thread block per chunk.
// ===========================================================================
__global__ void __launch_bounds__(256) dn_phase1(
    const float* __restrict__ q, const float* __restrict__ k,
    const float* __restrict__ v, const float* __restrict__ beta)
{
    __shared__ float sQ[32 * 68], sK[32 * 68], sV[32 * 68];
    __shared__ float sA[32 * 33];
    __shared__ float sRinv[64], sBeta[32];

    const int tid  = threadIdx.x;
    const int lane = tid & 31;
    const int wp   = tid >> 5;
    const size_t g = blockIdx.x;

    const uint32_t aQ = s2u(sQ), aK = s2u(sK), aV = s2u(sV);

    const float4* qb = (const float4*)(q + g * 2048);
    const float4* kb = (const float4*)(k + g * 2048);
    const float4* vb = (const float4*)(v + g * 2048);
#pragma unroll
    for (int it = 0; it < 2; ++it) {
        int f  = tid + it * 256;
        int so = (f >> 4) * 68 + ((f & 15) << 2);
        *(float4*)&sQ[so] = qb[f];
        *(float4*)&sK[so] = kb[f];
        *(float4*)&sV[so] = vb[f];
    }
    if (tid < 32) sBeta[tid] = beta[g * 32 + tid];
    __syncthreads();

    if (tid < 64) {
        const float4* rp = (const float4*)((tid < 32) ? (sQ + tid * 68) : (sK + (tid - 32) * 68));
        float s = 1e-6f;
#pragma unroll
        for (int m = 0; m < 16; ++m) {
            float4 a = rp[m];
            s = fmaf(a.x, a.x, s); s = fmaf(a.y, a.y, s);
            s = fmaf(a.z, a.z, s); s = fmaf(a.w, a.w, s);
        }
        sRinv[tid] = rsqrtf(s);
    }
    __syncthreads();
    for (int e = tid; e < 2048; e += 256) {
        int r = e >> 6, d = e & 63;
        sQ[r * 68 + d] *= sRinv[r];
        sK[r * 68 + d] *= sRinv[32 + r];
    }
    __syncthreads();

    // ---- A (strict lower, -beta_i kn_i.kn_j) and Lc = tril(qn kn^T) ----------
    {
        const int i0 = wp * 4;
        u64 a2A[4] = {0, 0, 0, 0}, a2L[4] = {0, 0, 0, 0};
#pragma unroll 4
        for (int dd = 0; dd < 16; ++dd) {
            u64 kj0, kj1;
            ldsv2(kj0, kj1, aK + (uint32_t)(lane * 272 + dd * 16));
#pragma unroll
            for (int e = 0; e < 4; ++e) {
                u64 ki0, ki1, qi0, qi1;
                ldsv2(ki0, ki1, aK + (uint32_t)((i0 + e) * 272 + dd * 16));   // broadcast
                ldsv2(qi0, qi1, aQ + (uint32_t)((i0 + e) * 272 + dd * 16));   // broadcast
                a2A[e] = fma2(ki0, kj0, a2A[e]);  a2A[e] = fma2(ki1, kj1, a2A[e]);
                a2L[e] = fma2(qi0, kj0, a2L[e]);  a2L[e] = fma2(qi1, kj1, a2L[e]);
            }
        }
        float* g_Lc = (float*)g_Lc4 + g * 1024;
#pragma unroll
        for (int e = 0; e < 4; ++e) {
            int i = i0 + e;
            sA[i * 33 + lane]   = (lane <  i) ? (-sBeta[i] * hadd2(a2A[e])) : 0.0f;
            g_Lc[i * 32 + lane] = (lane <= i) ? hadd2(a2L[e]) : 0.0f;
        }
    }
    __syncthreads();

    // ---- forward substitution: sA -> T = (I-A)^{-1} - I (strict lower) -------
    if (wp == 0) {
        for (int i = 1; i < 32; ++i) {
            float r   = sA[i * 33 + lane];
            float val = r;
            for (int j = 1; j < i; ++j) {
                float aij = __shfl_sync(0xffffffffu, r, j);
                if (lane < j) val = fmaf(aij, sA[j * 33 + lane], val);
            }
            sA[i * 33 + lane] = val;
            __syncwarp();
        }
    }
    __syncthreads();

    for (int e = tid; e < 1024; e += 256) {
        int i = e >> 5, j = e & 31;
        sA[i * 33 + j] *= sBeta[j];
    }
    __syncthreads();

    // ---- u = M @ (beta v), w = M @ (beta kn); M = I + T' ---------------------
#pragma unroll
    for (int p = 0; p < 4; ++p) {
        const bool isU = (p < 2);
        const int dcb  = p * 32 + wp * 4;
        const int db   = isU ? dcb : (dcb - 64);
        const uint32_t aX = isU ? aV : aK;
        float bi = sBeta[lane];
        u64 b2 = pack2(bi, bi);
        u64 x01, x23;
        ldsv2(x01, x23, aX + (uint32_t)(lane * 272 + db * 4));
        u64 a01 = mul2(b2, x01), a23 = mul2(b2, x23);
#pragma unroll 8
        for (int j = 0; j < 32; ++j) {
            float t = sA[lane * 33 + j];                 // zero for j >= lane
            u64 t2 = pack2(t, t);
            ldsv2(x01, x23, aX + (uint32_t)(j * 272 + db * 4));  // broadcast
            a01 = fma2(t2, x01, a01);
            a23 = fma2(t2, x23, a23);
        }
        float2 r01 = unpack2(a01), r23 = unpack2(a23);
        if (isU) {
            // store u as column pairs: [cpair][i][2], cpair = db/2 and db/2+1
            float* uP = (float*)g_uP4 + g * 2048;
            *(float2*)&uP[(db >> 1) * 64 + lane * 2]       = r01;
            *(float2*)&uP[((db >> 1) + 1) * 64 + lane * 2] = r23;
        } else {
            g_w4[g * 512 + lane * 16 + (db >> 2)] = make_float4(-r01.x, -r01.y, -r23.x, -r23.y);
        }
    }

    // ---- store qn row-major, kT [d][i] ---------------------------------------
    {
        float* g_qn = (float*)g_qn4 + g * 2048;
        float* g_kT = (float*)g_kT4 + g * 2048;
        for (int e = tid; e < 2048; e += 256) {
            int r = e >> 6, d = e & 63;
            g_qn[e] = sQ[r * 68 + d];
        }
        for (int f = tid; f < 2048; f += 256) {
            int d = f >> 5, i = f & 31;
            g_kT[f] = sK[i * 68 + d];
        }
    }
}

// ===========================================================================
// Phase 2: sequential scan. 128 blocks = 32 chains x 4 dv-splits (16 cols).
// Warp wp owns dv cols c0, c0+1. f32x2 over the REDUCTION axis:
//   u/o accumulate over d-parity; dS/oL accumulate over j-parity.
// S mirror is column-major mS[c][d] -> broadcast LDS.128 reads.
// Strides: q/w rows 272B (17x16B), kT/Lc rows 144B (9x16B): conflict-free.
// ===========================================================================
#define P2_QD    0          // q rows: 32 x 272B
#define P2_WD    8704       // w rows: 32 x 272B
#define P2_KT    17408      // kT rows: 64 x 144B
#define P2_LC    26624      // Lc rows: 32 x 144B
#define P2_BUF   31232      // per-buffer bytes
#define P2_MS    62464      // mirror: 8 warps x 2 x 64 floats (512B/warp)
#define P2_SMEM  66560

__global__ void __launch_bounds__(256) dn_phase2(float* __restrict__ out, int wantS)
{
    extern __shared__ float smem[];
    const uint32_t sb = s2u(smem);

    const int tid  = threadIdx.x;
    const int lane = tid & 31;
    const int wp   = tid >> 5;
    const int bh   = blockIdx.x >> 2;
    const int c0   = (blockIdx.x & 3) * 16 + wp * 2;
    const uint32_t ms0 = sb + P2_MS + (uint32_t)wp * 512;        // S[c0][0..63]
    const uint32_t ms1 = ms0 + 256;                               // S[c1][0..63]

    // zero mirror
    sts_f32(ms0 + (uint32_t)lane * 4, 0.f);
    sts_f32(ms0 + (uint32_t)(lane + 32) * 4, 0.f);
    sts_f32(ms1 + (uint32_t)lane * 4, 0.f);
    sts_f32(ms1 + (uint32_t)(lane + 32) * 4, 0.f);

    float S00 = 0.f, S01 = 0.f, S10 = 0.f, S11 = 0.f;  // S[lane][c0,c1], S[lane+32][c0,c1]

    const size_t gbase = (size_t)bh * 256;
    const float* uP = (const float*)g_uP4;

    float4 rq0, rq1, rw0, rw1, rt0, rt1, rl;
    float2 ru;

#define LOAD_REGS(T) do {                                                      \
    size_t g_ = gbase + (size_t)(T);                                           \
    rq0 = g_qn4[g_ * 512 + tid]; rq1 = g_qn4[g_ * 512 + tid + 256];            \
    rw0 = g_w4 [g_ * 512 + tid]; rw1 = g_w4 [g_ * 512 + tid + 256];            \
    rt0 = g_kT4[g_ * 512 + tid]; rt1 = g_kT4[g_ * 512 + tid + 256];            \
    rl  = g_Lc4[g_ * 256 + tid];                                               \
    ru  = *(const float2*)&uP[g_ * 2048 + (size_t)(c0 >> 1) * 64 + lane * 2];  \
} while (0)

#define STORE_SMEM(BUF) do {                                                   \
    uint32_t bb = sb + (uint32_t)(BUF) * P2_BUF;                               \
    { int r = tid >> 4, d4 = (tid & 15);                                       \
      uint32_t qa = bb + P2_QD + (uint32_t)(r * 272 + d4 * 16);                \
      sts_v4(qa, rq0);  sts_v4(qa + 16 * 272, rq1);                            \
      uint32_t wa = bb + P2_WD + (uint32_t)(r * 272 + d4 * 16);                \
      sts_v4(wa, rw0);  sts_v4(wa + 16 * 272, rw1); }                          \
    { int d = tid >> 3, i4 = (tid & 7);                                        \
      uint32_t ka = bb + P2_KT + (uint32_t)(d * 144 + i4 * 16);                \
      sts_v4(ka, rt0);  sts_v4(ka + 32 * 144, rt1);                            \
      uint32_t la = bb + P2_LC + (uint32_t)(d * 144 + i4 * 16);                \
      sts_v4(la, rl); }                                                        \
} while (0)

    LOAD_REGS(0);
    STORE_SMEM(0);
    float cu0 = ru.x, cu1 = ru.y;
    __syncthreads();

    for (int t = 0; t < 256; ++t) {
        const uint32_t bb = sb + (uint32_t)(t & 1) * P2_BUF;

        if (t + 1 < 256) LOAD_REGS(t + 1);    // LDG overlaps compute

        // ---- u = u0 + (-w)@S ; o = q@S (f32x2 over d-parity) ------------------
        const uint32_t qrow = bb + P2_QD + (uint32_t)lane * 272;
        const uint32_t wrow = bb + P2_WD + (uint32_t)lane * 272;
        u64 au0 = 0, au1 = 0, ao0 = 0, ao1 = 0;
#pragma unroll
        for (int i = 0; i < 16; ++i) {
            u64 w01, w23, q01, q23, s0a, s0b, s1a, s1b;
            ldsv2(w01, w23, wrow + (uint32_t)i * 16);
            ldsv2(q01, q23, qrow + (uint32_t)i * 16);
            ldsv2(s0a, s0b, ms0 + (uint32_t)i * 16);   // broadcast
            ldsv2(s1a, s1b, ms1 + (uint32_t)i * 16);   // broadcast
            au0 = fma2(w01, s0a, au0);  au0 = fma2(w23, s0b, au0);
            au1 = fma2(w01, s1a, au1);  au1 = fma2(w23, s1b, au1);
            ao0 = fma2(q01, s0a, ao0);  ao0 = fma2(q23, s0b, ao0);
            ao1 = fma2(q01, s1a, ao1);  ao1 = fma2(q23, s1b, ao1);
        }
        float u0 = cu0 + hadd2(au0);
        float u1 = cu1 + hadd2(au1);

        // ---- o += Lc@u ; dS = k^T@u (f32x2 over j-parity) ---------------------
        const uint32_t lrow  = bb + P2_LC + (uint32_t)lane * 144;
        const uint32_t krow0 = bb + P2_KT + (uint32_t)lane * 144;
        const uint32_t krow1 = bb + P2_KT + (uint32_t)(lane + 32) * 144;
        u64 dS00 = 0, dS01 = 0, dS10 = 0, dS11 = 0, aoL0 = 0, aoL1 = 0;
#pragma unroll
        for (int j4 = 0; j4 < 8; ++j4) {
            u64 L01, L23, k0a, k0b, k1a, k1b;
            ldsv2(L01, L23, lrow  + (uint32_t)j4 * 16);
            ldsv2(k0a, k0b, krow0 + (uint32_t)j4 * 16);
            ldsv2(k1a, k1b, krow1 + (uint32_t)j4 * 16);
            int j = j4 * 4;
            u64 p0 = pack2(__shfl_sync(0xffffffffu, u0, j),
                           __shfl_sync(0xffffffffu, u0, j + 1));
            u64 p1 = pack2(__shfl_sync(0xffffffffu, u1, j),
                           __shfl_sync(0xffffffffu, u1, j + 1));
            aoL0 = fma2(L01, p0, aoL0);  aoL1 = fma2(L01, p1, aoL1);
            dS00 = fma2(k0a, p0, dS00);  dS01 = fma2(k0a, p1, dS01);
            dS10 = fma2(k1a, p0, dS10);  dS11 = fma2(k1a, p1, dS11);
            u64 p0b = pack2(__shfl_sync(0xffffffffu, u0, j + 2),
                            __shfl_sync(0xffffffffu, u0, j + 3));
            u64 p1b = pack2(__shfl_sync(0xffffffffu, u1, j + 2),
                            __shfl_sync(0xffffffffu, u1, j + 3));
            aoL0 = fma2(L23, p0b, aoL0);  aoL1 = fma2(L23, p1b, aoL1);
            dS00 = fma2(k0b, p0b, dS00);  dS01 = fma2(k0b, p1b, dS01);
            dS10 = fma2(k1b, p0b, dS10);  dS11 = fma2(k1b, p1b, dS11);
        }

        // fold partial sums
        S00 += hadd2(dS00);  S01 += hadd2(dS01);
        S10 += hadd2(dS10);  S11 += hadd2(dS11);
        float o0 = hadd2(ao0) + hadd2(aoL0);
        float o1 = hadd2(ao1) + hadd2(aoL1);

        // update mirror (warp-private, conflict-free scalar STS)
        sts_f32(ms0 + (uint32_t)lane * 4, S00);
        sts_f32(ms1 + (uint32_t)lane * 4, S01);
        sts_f32(ms0 + (uint32_t)(lane + 32) * 4, S10);
        sts_f32(ms1 + (uint32_t)(lane + 32) * 4, S11);

        size_t orow = ((size_t)bh * 8192 + (size_t)t * 32 + lane) * 64 + c0;
        *(float2*)(out + orow) = make_float2(o0, o1);

        if (t + 1 < 256) {
            STORE_SMEM((t + 1) & 1);
            cu0 = ru.x; cu1 = ru.y;
        }
        __syncthreads();
    }

    if (wantS) {
        size_t so = (size_t)O_ELEMS + (size_t)bh * 4096 + (size_t)lane * 64 + c0;
        *(float2*)(out + so)        = make_float2(S00, S01);
        *(float2*)(out + so + 2048) = make_float2(S10, S11);
    }
#undef LOAD_REGS
#undef STORE_SMEM
}

// ===========================================================================
extern "C" void kernel_launch(void* const* d_in, const int* in_sizes, int n_in,
                              void* d_out, int out_size)
{
    const float* q    = (const float*)d_in[0];
    const float* k    = (const float*)d_in[1];
    const float* v    = (const float*)d_in[2];
    const float* beta = (const float*)d_in[3];
    float* out = (float*)d_out;
    int wantS = (out_size > O_ELEMS) ? 1 : 0;

    cudaFuncSetAttribute(dn_phase2, cudaFuncAttributeMaxDynamicSharedMemorySize, P2_SMEM);

    dn_phase1<<<G_CHUNKS, 256>>>(q, k, v, beta);
    dn_phase2<<<128, 256, P2_SMEM>>>(out, wantS);
}

// round 5
// speedup vs baseline: 1.7374x; 1.3440x over previous
#include <cuda_runtime.h>
#include <cuda_bf16.h>
#include <cstdint>

typedef unsigned long long u64;

// Problem: b=4, h=8, L=8192, dk=dv=64, chunk=32. 32 chains x 256 chunks.
#define G_CHUNKS 8192
#define O_ELEMS  16777216   // 4*8*8192*64

// ---------------- scratch (device globals; allocation-free rule) -----------
__device__ float4 g_qn4[G_CHUNKS * 512];   // qn  [g][32][64] row-major
__device__ float4 g_w4 [G_CHUNKS * 512];   // -w  [g][32][64] row-major (NEGATED)
__device__ float4 g_kT4[G_CHUNKS * 512];   // k^T [g][64][32]
__device__ float4 g_uB4[G_CHUNKS * 512];   // u0  [g][split(4)][i(32)][c4(4)] float4
__device__ float4 g_Lc4[G_CHUNKS * 256];   // Lc  [g][32][32] (tril incl diag)

// ---------------- f32x2 / LDS helpers --------------------------------------
__device__ __forceinline__ u64 fma2(u64 a, u64 b, u64 c) {
    u64 d; asm("fma.rn.f32x2 %0, %1, %2, %3;" : "=l"(d) : "l"(a), "l"(b), "l"(c)); return d;
}
__device__ __forceinline__ u64 mul2(u64 a, u64 b) {
    u64 d; asm("mul.rn.f32x2 %0, %1, %2;" : "=l"(d) : "l"(a), "l"(b)); return d;
}
__device__ __forceinline__ u64 pack2(float x, float y) {
    u64 d; asm("mov.b64 %0, {%1, %2};" : "=l"(d) : "f"(x), "f"(y)); return d;
}
__device__ __forceinline__ float2 unpack2(u64 a) {
    float2 r; asm("mov.b64 {%0, %1}, %2;" : "=f"(r.x), "=f"(r.y) : "l"(a)); return r;
}
__device__ __forceinline__ float hadd2(u64 a) {
    float2 r = unpack2(a); return r.x + r.y;
}
__device__ __forceinline__ void ldsv2(u64& a, u64& b, uint32_t addr) {
    asm volatile("ld.shared.v2.u64 {%0, %1}, [%2];" : "=l"(a), "=l"(b) : "r"(addr));
}
__device__ __forceinline__ void sts_f32(uint32_t addr, float v) {
    asm volatile("st.shared.f32 [%0], %1;" :: "r"(addr), "f"(v));
}
__device__ __forceinline__ void sts_v4(uint32_t addr, float4 v) {
    asm volatile("st.shared.v4.f32 [%0], {%1,%2,%3,%4};"
                 :: "r"(addr), "f"(v.x), "f"(v.y), "f"(v.z), "f"(v.w));
}
__device__ __forceinline__ uint32_t s2u(const void* p) {
    return (uint32_t)__cvta_generic_to_shared(p);
}

// ===========================================================================
// Phase 1: per-chunk preprocessing. One 256-thread block per chunk.
// (unchanged from R4 except the u0 output layout)
// ===========================================================================
__global__ void __launch_bounds__(256) dn_phase1(
    const float* __restrict__ q, const float* __restrict__ k,
    const float* __restrict__ v, const float* __restrict__ beta)
{
    __shared__ float sQ[32 * 68], sK[32 * 68], sV[32 * 68];
    __shared__ float sA[32 * 33];
    __shared__ float sRinv[64], sBeta[32];

    const int tid  = threadIdx.x;
    const int lane = tid & 31;
    const int wp   = tid >> 5;
    const size_t g = blockIdx.x;

    const uint32_t aQ = s2u(sQ), aK = s2u(sK), aV = s2u(sV);

    const float4* qb = (const float4*)(q + g * 2048);
    const float4* kb = (const float4*)(k + g * 2048);
    const float4* vb = (const float4*)(v + g * 2048);
#pragma unroll
    for (int it = 0; it < 2; ++it) {
        int f  = tid + it * 256;
        int so = (f >> 4) * 68 + ((f & 15) << 2);
        *(float4*)&sQ[so] = qb[f];
        *(float4*)&sK[so] = kb[f];
        *(float4*)&sV[so] = vb[f];
    }
    if (tid < 32) sBeta[tid] = beta[g * 32 + tid];
    __syncthreads();

    if (tid < 64) {
        const float4* rp = (const float4*)((tid < 32) ? (sQ + tid * 68) : (sK + (tid - 32) * 68));
        float s = 1e-6f;
#pragma unroll
        for (int m = 0; m < 16; ++m) {
            float4 a = rp[m];
            s = fmaf(a.x, a.x, s); s = fmaf(a.y, a.y, s);
            s = fmaf(a.z, a.z, s); s = fmaf(a.w, a.w, s);
        }
        sRinv[tid] = rsqrtf(s);
    }
    __syncthreads();
    for (int e = tid; e < 2048; e += 256) {
        int r = e >> 6, d = e & 63;
        sQ[r * 68 + d] *= sRinv[r];
        sK[r * 68 + d] *= sRinv[32 + r];
    }
    __syncthreads();

    {
        const int i0 = wp * 4;
        u64 a2A[4] = {0, 0, 0, 0}, a2L[4] = {0, 0, 0, 0};
#pragma unroll 4
        for (int dd = 0; dd < 16; ++dd) {
            u64 kj0, kj1;
            ldsv2(kj0, kj1, aK + (uint32_t)(lane * 272 + dd * 16));
#pragma unroll
            for (int e = 0; e < 4; ++e) {
                u64 ki0, ki1, qi0, qi1;
                ldsv2(ki0, ki1, aK + (uint32_t)((i0 + e) * 272 + dd * 16));
                ldsv2(qi0, qi1, aQ + (uint32_t)((i0 + e) * 272 + dd * 16));
                a2A[e] = fma2(ki0, kj0, a2A[e]);  a2A[e] = fma2(ki1, kj1, a2A[e]);
                a2L[e] = fma2(qi0, kj0, a2L[e]);  a2L[e] = fma2(qi1, kj1, a2L[e]);
            }
        }
        float* g_Lc = (float*)g_Lc4 + g * 1024;
#pragma unroll
        for (int e = 0; e < 4; ++e) {
            int i = i0 + e;
            sA[i * 33 + lane]   = (lane <  i) ? (-sBeta[i] * hadd2(a2A[e])) : 0.0f;
            g_Lc[i * 32 + lane] = (lane <= i) ? hadd2(a2L[e]) : 0.0f;
        }
    }
    __syncthreads();

    if (wp == 0) {
        for (int i = 1; i < 32; ++i) {
            float r   = sA[i * 33 + lane];
            float val = r;
            for (int j = 1; j < i; ++j) {
                float aij = __shfl_sync(0xffffffffu, r, j);
                if (lane < j) val = fmaf(aij, sA[j * 33 + lane], val);
            }
            sA[i * 33 + lane] = val;
            __syncwarp();
        }
    }
    __syncthreads();

    for (int e = tid; e < 1024; e += 256) {
        int i = e >> 5, j = e & 31;
        sA[i * 33 + j] *= sBeta[j];
    }
    __syncthreads();

#pragma unroll
    for (int p = 0; p < 4; ++p) {
        const bool isU = (p < 2);
        const int dcb  = p * 32 + wp * 4;
        const int db   = isU ? dcb : (dcb - 64);
        const uint32_t aX = isU ? aV : aK;
        float bi = sBeta[lane];
        u64 b2 = pack2(bi, bi);
        u64 x01, x23;
        ldsv2(x01, x23, aX + (uint32_t)(lane * 272 + db * 4));
        u64 a01 = mul2(b2, x01), a23 = mul2(b2, x23);
#pragma unroll 8
        for (int j = 0; j < 32; ++j) {
            float t = sA[lane * 33 + j];                 // zero for j >= lane
            u64 t2 = pack2(t, t);
            ldsv2(x01, x23, aX + (uint32_t)(j * 272 + db * 4));
            a01 = fma2(t2, x01, a01);
            a23 = fma2(t2, x23, a23);
        }
        float2 r01 = unpack2(a01), r23 = unpack2(a23);
        if (isU) {
            // u0 layout: [g][split = db>>4][i = lane][c4 = (db&15)>>2] float4
            g_uB4[g * 512 + (size_t)(db >> 4) * 128 + lane * 4 + ((db & 15) >> 2)] =
                make_float4(r01.x, r01.y, r23.x, r23.y);
        } else {
            g_w4[g * 512 + lane * 16 + (db >> 2)] = make_float4(-r01.x, -r01.y, -r23.x, -r23.y);
        }
    }

    {
        float* g_qn = (float*)g_qn4 + g * 2048;
        float* g_kT = (float*)g_kT4 + g * 2048;
        for (int e = tid; e < 2048; e += 256) {
            int r = e >> 6, d = e & 63;
            g_qn[e] = sQ[r * 68 + d];
        }
        for (int f = tid; f < 2048; f += 256) {
            int d = f >> 5, i = f & 31;
            g_kT[f] = sK[i * 68 + d];
        }
    }
}

// ===========================================================================
// Phase 2: sequential scan, warp-specialized.
// 128 blocks = 32 chains x 4 splits (16 cols). 8 warps:
//   warps 0-3: compute. Warp wp owns 4 dv cols c0 = split*16 + wp*4.
//   warps 4-7: staging (LDG -> STS), double-buffered, prefetch 1 chunk ahead.
// Row strides: q/w 272B (17 units), kT/Lc/u0 144B (9 units) -> conflict-free.
// ===========================================================================
#define P2_QD    0          // q  rows: 32 x 272B
#define P2_WD    8704       // -w rows: 32 x 272B
#define P2_KT    17408      // kT rows: 64 x 144B
#define P2_LC    26624      // Lc rows: 32 x 144B
#define P2_U0    31232      // u0 rows: 32 x 144B (only 64B used per row)
#define P2_BUF   35840
#define P2_MS    71680      // S mirror: 4 warps x (4 cols x 64 floats) = 4KB
#define P2_UL    75776      // u local : 4 warps x (4 cols x 32 floats) = 2KB
#define P2_SMEM  77824

__global__ void __launch_bounds__(256) dn_phase2(float* __restrict__ out, int wantS)
{
    extern __shared__ float smem[];
    const uint32_t sb = s2u(smem);

    const int tid  = threadIdx.x;
    const int lane = tid & 31;
    const int wp   = tid >> 5;
    const int bh   = blockIdx.x >> 2;
    const int sp   = blockIdx.x & 3;
    const size_t gbase = (size_t)bh * 256;

    if (wp >= 4) {
        // =================== STAGING ROLE (warps 4-7) ========================
        const int st = tid - 128;          // 0..127
        float4 rq[4], rw[4], rt[4], rl[2], ru;

#define P2_LOADS(T) do {                                                       \
    size_t g_ = gbase + (size_t)(T);                                           \
    rq[0] = g_qn4[g_ * 512 + st];        rq[1] = g_qn4[g_ * 512 + st + 128];   \
    rq[2] = g_qn4[g_ * 512 + st + 256];  rq[3] = g_qn4[g_ * 512 + st + 384];   \
    rw[0] = g_w4 [g_ * 512 + st];        rw[1] = g_w4 [g_ * 512 + st + 128];   \
    rw[2] = g_w4 [g_ * 512 + st + 256];  rw[3] = g_w4 [g_ * 512 + st + 384];   \
    rt[0] = g_kT4[g_ * 512 + st];        rt[1] = g_kT4[g_ * 512 + st + 128];   \
    rt[2] = g_kT4[g_ * 512 + st + 256];  rt[3] = g_kT4[g_ * 512 + st + 384];   \
    rl[0] = g_Lc4[g_ * 256 + st];        rl[1] = g_Lc4[g_ * 256 + st + 128];   \
    ru    = g_uB4[g_ * 512 + (size_t)sp * 128 + st];                           \
} while (0)

#define P2_STORES(BUF) do {                                                    \
    uint32_t bb = sb + (uint32_t)(BUF) * P2_BUF;                               \
    _Pragma("unroll")                                                          \
    for (int m = 0; m < 4; ++m) {                                              \
        int f = st + m * 128;                                                  \
        sts_v4(bb + P2_QD + (uint32_t)((f >> 4) * 272 + (f & 15) * 16), rq[m]);\
        sts_v4(bb + P2_WD + (uint32_t)((f >> 4) * 272 + (f & 15) * 16), rw[m]);\
        sts_v4(bb + P2_KT + (uint32_t)((f >> 3) * 144 + (f & 7)  * 16), rt[m]);\
    }                                                                          \
    _Pragma("unroll")                                                          \
    for (int m = 0; m < 2; ++m) {                                              \
        int f = st + m * 128;                                                  \
        sts_v4(bb + P2_LC + (uint32_t)((f >> 3) * 144 + (f & 7)  * 16), rl[m]);\
    }                                                                          \
    sts_v4(bb + P2_U0 + (uint32_t)((st >> 2) * 144 + (st & 3) * 16), ru);      \
} while (0)

        P2_LOADS(0);
        P2_STORES(0);
        P2_LOADS(1);
        __syncthreads();
        for (int t = 0; t < 256; ++t) {
            if (t + 1 < 256) P2_STORES((t + 1) & 1);   // regs loaded last iter
            if (t + 2 < 256) P2_LOADS(t + 2);          // full chunk to arrive
            __syncthreads();
        }
        return;
#undef P2_LOADS
#undef P2_STORES
    }

    // ====================== COMPUTE ROLE (warps 0-3) =========================
    const int c0 = sp * 16 + wp * 4;
    const uint32_t msb = sb + P2_MS + (uint32_t)wp * 1024;   // S mirror, col-major
    const uint32_t ulb = sb + P2_UL + (uint32_t)wp * 512;    // u local, col-major

#pragma unroll
    for (int c = 0; c < 4; ++c) {
        sts_f32(msb + (uint32_t)c * 256 + (uint32_t)lane * 4, 0.f);
        sts_f32(msb + (uint32_t)c * 256 + (uint32_t)(lane + 32) * 4, 0.f);
    }
    float S0[4] = {0.f, 0.f, 0.f, 0.f};   // S[lane][c]
    float S1[4] = {0.f, 0.f, 0.f, 0.f};   // S[lane+32][c]

    __syncthreads();   // matches staging warps' first barrier

    for (int t = 0; t < 256; ++t) {
        const uint32_t bb = sb + (uint32_t)(t & 1) * P2_BUF;

        // ---- u = u0 + (-w)@S ; o = q@S  (f32x2 over d-parity, 4 cols) -------
        const uint32_t wrow = bb + P2_WD + (uint32_t)lane * 272;
        const uint32_t qrow = bb + P2_QD + (uint32_t)lane * 272;
        u64 au[4] = {0, 0, 0, 0}, ao[4] = {0, 0, 0, 0};
#pragma unroll
        for (int i = 0; i < 16; ++i) {
            u64 w01, w23, q01, q23;
            ldsv2(w01, w23, wrow + (uint32_t)i * 16);
            ldsv2(q01, q23, qrow + (uint32_t)i * 16);
#pragma unroll
            for (int c = 0; c < 4; ++c) {
                u64 sa, sbv;
                ldsv2(sa, sbv, msb + (uint32_t)c * 256 + (uint32_t)i * 16);  // broadcast
                au[c] = fma2(w01, sa, au[c]);  au[c] = fma2(w23, sbv, au[c]);
                ao[c] = fma2(q01, sa, ao[c]);  ao[c] = fma2(q23, sbv, ao[c]);
            }
        }
        u64 ua, ub;
        ldsv2(ua, ub, bb + P2_U0 + (uint32_t)lane * 144 + (uint32_t)wp * 16);
        float2 u01 = unpack2(ua), u23 = unpack2(ub);
        float uu[4];
        uu[0] = u01.x + hadd2(au[0]);  uu[1] = u01.y + hadd2(au[1]);
        uu[2] = u23.x + hadd2(au[2]);  uu[3] = u23.y + hadd2(au[3]);

        // share u within warp via col-major smem (for broadcast j-pairs)
#pragma unroll
        for (int c = 0; c < 4; ++c)
            sts_f32(ulb + (uint32_t)c * 128 + (uint32_t)lane * 4, uu[c]);
        __syncwarp();

        // ---- o += Lc@u ; dS = k^T@u  (f32x2 over j-parity) -------------------
        const uint32_t lrow  = bb + P2_LC + (uint32_t)lane * 144;
        const uint32_t krow0 = bb + P2_KT + (uint32_t)lane * 144;
        const uint32_t krow1 = bb + P2_KT + (uint32_t)(lane + 32) * 144;
        u64 aoL[4] = {0, 0, 0, 0}, d0[4] = {0, 0, 0, 0}, d1[4] = {0, 0, 0, 0};
#pragma unroll
        for (int j4 = 0; j4 < 8; ++j4) {
            u64 L01, L23, k0a, k0b, k1a, k1b;
            ldsv2(L01, L23, lrow  + (uint32_t)j4 * 16);
            ldsv2(k0a, k0b, krow0 + (uint32_t)j4 * 16);
            ldsv2(k1a, k1b, krow1 + (uint32_t)j4 * 16);
#pragma unroll
            for (int c = 0; c < 4; ++c) {
                u64 up01, up23;
                ldsv2(up01, up23, ulb + (uint32_t)c * 128 + (uint32_t)j4 * 16);  // broadcast
                aoL[c] = fma2(L01, up01, aoL[c]);  aoL[c] = fma2(L23, up23, aoL[c]);
                d0[c]  = fma2(k0a, up01, d0[c]);   d0[c]  = fma2(k0b, up23, d0[c]);
                d1[c]  = fma2(k1a, up01, d1[c]);   d1[c]  = fma2(k1b, up23, d1[c]);
            }
        }

        float o[4];
#pragma unroll
        for (int c = 0; c < 4; ++c) {
            S0[c] += hadd2(d0[c]);
            S1[c] += hadd2(d1[c]);
            o[c] = hadd2(ao[c]) + hadd2(aoL[c]);
            sts_f32(msb + (uint32_t)c * 256 + (uint32_t)lane * 4, S0[c]);
            sts_f32(msb + (uint32_t)c * 256 + (uint32_t)(lane + 32) * 4, S1[c]);
        }

        size_t orow = ((size_t)bh * 8192 + (size_t)t * 32 + lane) * 64 + c0;
        *(float4*)(out + orow) = make_float4(o[0], o[1], o[2], o[3]);

        __syncthreads();   // next buffer staged; mirror writes visible in-warp
    }

    if (wantS) {
        size_t so = (size_t)O_ELEMS + (size_t)bh * 4096 + (size_t)lane * 64 + c0;
        *(float4*)(out + so)        = make_float4(S0[0], S0[1], S0[2], S0[3]);
        *(float4*)(out + so + 2048) = make_float4(S1[0], S1[1], S1[2], S1[3]);
    }
}

// ===========================================================================
extern "C" void kernel_launch(void* const* d_in, const int* in_sizes, int n_in,
                              void* d_out, int out_size)
{
    const float* q    = (const float*)d_in[0];
    const float* k    = (const float*)d_in[1];
    const float* v    = (const float*)d_in[2];
    const float* beta = (const float*)d_in[3];
    float* out = (float*)d_out;
    int wantS = (out_size > O_ELEMS) ? 1 : 0;

    cudaFuncSetAttribute(dn_phase2, cudaFuncAttributeMaxDynamicSharedMemorySize, P2_SMEM);

    dn_phase1<<<G_CHUNKS, 256>>>(q, k, v, beta);
    dn_phase2<<<128, 256, P2_SMEM>>>(out, wantS);
}

// round 6
// speedup vs baseline: 1.9178x; 1.1039x over previous
#include <cuda_runtime.h>
#include <cuda_bf16.h>
#include <cstdint>

typedef unsigned long long u64;

// Problem: b=4, h=8, L=8192, dk=dv=64, chunk=32. 32 chains x 256 chunks.
#define G_CHUNKS 8192
#define O_ELEMS  16777216   // 4*8*8192*64

// ---------------- scratch (device globals; allocation-free rule) -----------
__device__ float4 g_qn4[G_CHUNKS * 512];   // qn  [g][32][64] row-major
__device__ float4 g_w4 [G_CHUNKS * 512];   // -w  [g][32][64] row-major (NEGATED)
__device__ float4 g_kT4[G_CHUNKS * 512];   // k^T [g][64][32]
__device__ float4 g_uB4[G_CHUNKS * 512];   // u0  [g][split(4)][i(32)][c4(4)] float4
__device__ float4 g_Lc4[G_CHUNKS * 256];   // Lc  [g][32][32] (tril incl diag)

// ---------------- f32x2 / LDS helpers --------------------------------------
__device__ __forceinline__ u64 fma2(u64 a, u64 b, u64 c) {
    u64 d; asm("fma.rn.f32x2 %0, %1, %2, %3;" : "=l"(d) : "l"(a), "l"(b), "l"(c)); return d;
}
__device__ __forceinline__ u64 mul2(u64 a, u64 b) {
    u64 d; asm("mul.rn.f32x2 %0, %1, %2;" : "=l"(d) : "l"(a), "l"(b)); return d;
}
__device__ __forceinline__ u64 pack2(float x, float y) {
    u64 d; asm("mov.b64 %0, {%1, %2};" : "=l"(d) : "f"(x), "f"(y)); return d;
}
__device__ __forceinline__ float2 unpack2(u64 a) {
    float2 r; asm("mov.b64 {%0, %1}, %2;" : "=f"(r.x), "=f"(r.y) : "l"(a)); return r;
}
__device__ __forceinline__ float hadd2(u64 a) {
    float2 r = unpack2(a); return r.x + r.y;
}
__device__ __forceinline__ void ldsv2(u64& a, u64& b, uint32_t addr) {
    asm volatile("ld.shared.v2.u64 {%0, %1}, [%2];" : "=l"(a), "=l"(b) : "r"(addr));
}
__device__ __forceinline__ void sts_f32(uint32_t addr, float v) {
    asm volatile("st.shared.f32 [%0], %1;" :: "r"(addr), "f"(v));
}
__device__ __forceinline__ void sts_v4(uint32_t addr, float4 v) {
    asm volatile("st.shared.v4.f32 [%0], {%1,%2,%3,%4};"
                 :: "r"(addr), "f"(v.x), "f"(v.y), "f"(v.z), "f"(v.w));
}
__device__ __forceinline__ uint32_t s2u(const void* p) {
    return (uint32_t)__cvta_generic_to_shared(p);
}

// ===========================================================================
// Phase 1: per-chunk preprocessing. One 256-thread block per chunk.
// ===========================================================================
__global__ void __launch_bounds__(256) dn_phase1(
    const float* __restrict__ q, const float* __restrict__ k,
    const float* __restrict__ v, const float* __restrict__ beta)
{
    __shared__ float sQ[32 * 68], sK[32 * 68], sV[32 * 68];
    __shared__ float sA[32 * 33];
    __shared__ float sRinv[64], sBeta[32];

    const int tid  = threadIdx.x;
    const int lane = tid & 31;
    const int wp   = tid >> 5;
    const size_t g = blockIdx.x;

    const uint32_t aQ = s2u(sQ), aK = s2u(sK), aV = s2u(sV);

    const float4* qb = (const float4*)(q + g * 2048);
    const float4* kb = (const float4*)(k + g * 2048);
    const float4* vb = (const float4*)(v + g * 2048);
#pragma unroll
    for (int it = 0; it < 2; ++it) {
        int f  = tid + it * 256;
        int so = (f >> 4) * 68 + ((f & 15) << 2);
        *(float4*)&sQ[so] = qb[f];
        *(float4*)&sK[so] = kb[f];
        *(float4*)&sV[so] = vb[f];
    }
    if (tid < 32) sBeta[tid] = beta[g * 32 + tid];
    __syncthreads();

    if (tid < 64) {
        const float4* rp = (const float4*)((tid < 32) ? (sQ + tid * 68) : (sK + (tid - 32) * 68));
        float s = 1e-6f;
#pragma unroll
        for (int m = 0; m < 16; ++m) {
            float4 a = rp[m];
            s = fmaf(a.x, a.x, s); s = fmaf(a.y, a.y, s);
            s = fmaf(a.z, a.z, s); s = fmaf(a.w, a.w, s);
        }
        sRinv[tid] = rsqrtf(s);
    }
    __syncthreads();
    for (int e = tid; e < 2048; e += 256) {
        int r = e >> 6, d = e & 63;
        sQ[r * 68 + d] *= sRinv[r];
        sK[r * 68 + d] *= sRinv[32 + r];
    }
    __syncthreads();

    // ---- A (strict lower, -beta_i kn_i.kn_j) and Lc = tril(qn kn^T) ----------
    {
        const int i0 = wp * 4;
        u64 a2A[4] = {0, 0, 0, 0}, a2L[4] = {0, 0, 0, 0};
#pragma unroll 4
        for (int dd = 0; dd < 16; ++dd) {
            u64 kj0, kj1;
            ldsv2(kj0, kj1, aK + (uint32_t)(lane * 272 + dd * 16));
#pragma unroll
            for (int e = 0; e < 4; ++e) {
                u64 ki0, ki1, qi0, qi1;
                ldsv2(ki0, ki1, aK + (uint32_t)((i0 + e) * 272 + dd * 16));
                ldsv2(qi0, qi1, aQ + (uint32_t)((i0 + e) * 272 + dd * 16));
                a2A[e] = fma2(ki0, kj0, a2A[e]);  a2A[e] = fma2(ki1, kj1, a2A[e]);
                a2L[e] = fma2(qi0, kj0, a2L[e]);  a2L[e] = fma2(qi1, kj1, a2L[e]);
            }
        }
        float* g_Lc = (float*)g_Lc4 + g * 1024;
#pragma unroll
        for (int e = 0; e < 4; ++e) {
            int i = i0 + e;
            sA[i * 33 + lane]   = (lane <  i) ? (-sBeta[i] * hadd2(a2A[e])) : 0.0f;
            g_Lc[i * 32 + lane] = (lane <= i) ? hadd2(a2L[e]) : 0.0f;
        }
    }
    __syncthreads();

    // ---- OVERLAP: warp 0 trisolve; warps 1-7 drain qn/kT to global -----------
    if (wp == 0) {
        // T = (I-A)^{-1} - I, in place. Rows strict-lower => sA[j][lane]=0 for
        // lane>=j, so no predicate needed. Same-lane smem deps only => no sync.
#pragma unroll
        for (int i = 1; i < 32; ++i) {
            float r = sA[i * 33 + lane];
            float v0 = r, v1 = 0.f, v2 = 0.f, v3 = 0.f;
#pragma unroll
            for (int j = 1; j < i; ++j) {
                float aij = __shfl_sync(0xffffffffu, r, j);
                float tj  = sA[j * 33 + lane];
                if ((j & 3) == 0)      v0 = fmaf(aij, tj, v0);
                else if ((j & 3) == 1) v1 = fmaf(aij, tj, v1);
                else if ((j & 3) == 2) v2 = fmaf(aij, tj, v2);
                else                   v3 = fmaf(aij, tj, v3);
            }
            sA[i * 33 + lane] = (v0 + v1) + (v2 + v3);
        }
    } else {
        float* g_qn = (float*)g_qn4 + g * 2048;
        float* g_kT = (float*)g_kT4 + g * 2048;
        for (int e = (wp - 1) * 32 + lane; e < 4096; e += 224) {
            if (e < 2048) {
                int r = e >> 6, d = e & 63;
                g_qn[e] = sQ[r * 68 + d];
            } else {
                int f = e - 2048;
                int d = f >> 5, i = f & 31;
                g_kT[f] = sK[i * 68 + d];
            }
        }
    }
    __syncthreads();

    // ---- fold beta into T columns --------------------------------------------
    for (int e = tid; e < 1024; e += 256) {
        int i = e >> 5, j = e & 31;
        sA[i * 33 + j] *= sBeta[j];
    }
    __syncthreads();

    // ---- u = M @ (beta v), w = M @ (beta kn); M = I + T' ---------------------
#pragma unroll
    for (int p = 0; p < 4; ++p) {
        const bool isU = (p < 2);
        const int dcb  = p * 32 + wp * 4;
        const int db   = isU ? dcb : (dcb - 64);
        const uint32_t aX = isU ? aV : aK;
        float bi = sBeta[lane];
        u64 b2 = pack2(bi, bi);
        u64 x01, x23;
        ldsv2(x01, x23, aX + (uint32_t)(lane * 272 + db * 4));
        u64 a01 = mul2(b2, x01), a23 = mul2(b2, x23);
#pragma unroll 8
        for (int j = 0; j < 32; ++j) {
            float t = sA[lane * 33 + j];                 // zero for j >= lane
            u64 t2 = pack2(t, t);
            ldsv2(x01, x23, aX + (uint32_t)(j * 272 + db * 4));
            a01 = fma2(t2, x01, a01);
            a23 = fma2(t2, x23, a23);
        }
        float2 r01 = unpack2(a01), r23 = unpack2(a23);
        if (isU) {
            // u0 layout: [g][split = db>>4][i = lane][c4 = (db&15)>>2] float4
            g_uB4[g * 512 + (size_t)(db >> 4) * 128 + lane * 4 + ((db & 15) >> 2)] =
                make_float4(r01.x, r01.y, r23.x, r23.y);
        } else {
            g_w4[g * 512 + lane * 16 + (db >> 2)] = make_float4(-r01.x, -r01.y, -r23.x, -r23.y);
        }
    }
}

// ===========================================================================
// Phase 2: sequential scan, warp-specialized.  (UNCHANGED from R5: 330 us)
// 128 blocks = 32 chains x 4 splits (16 cols). 8 warps:
//   warps 0-3: compute. Warp wp owns 4 dv cols c0 = split*16 + wp*4.
//   warps 4-7: staging (LDG -> STS), double-buffered, prefetch 1 chunk ahead.
// Row strides: q/w 272B (17 units), kT/Lc/u0 144B (9 units) -> conflict-free.
// ===========================================================================
#define P2_QD    0          // q  rows: 32 x 272B
#define P2_WD    8704       // -w rows: 32 x 272B
#define P2_KT    17408      // kT rows: 64 x 144B
#define P2_LC    26624      // Lc rows: 32 x 144B
#define P2_U0    31232      // u0 rows: 32 x 144B (only 64B used per row)
#define P2_BUF   35840
#define P2_MS    71680      // S mirror: 4 warps x (4 cols x 64 floats) = 4KB
#define P2_UL    75776      // u local : 4 warps x (4 cols x 32 floats) = 2KB
#define P2_SMEM  77824

__global__ void __launch_bounds__(256) dn_phase2(float* __restrict__ out, int wantS)
{
    extern __shared__ float smem[];
    const uint32_t sb = s2u(smem);

    const int tid  = threadIdx.x;
    const int lane = tid & 31;
    const int wp   = tid >> 5;
    const int bh   = blockIdx.x >> 2;
    const int sp   = blockIdx.x & 3;
    const size_t gbase = (size_t)bh * 256;

    if (wp >= 4) {
        // =================== STAGING ROLE (warps 4-7) ========================
        const int st = tid - 128;          // 0..127
        float4 rq[4], rw[4], rt[4], rl[2], ru;

#define P2_LOADS(T) do {                                                       \
    size_t g_ = gbase + (size_t)(T);                                           \
    rq[0] = g_qn4[g_ * 512 + st];        rq[1] = g_qn4[g_ * 512 + st + 128];   \
    rq[2] = g_qn4[g_ * 512 + st + 256];  rq[3] = g_qn4[g_ * 512 + st + 384];   \
    rw[0] = g_w4 [g_ * 512 + st];        rw[1] = g_w4 [g_ * 512 + st + 128];   \
    rw[2] = g_w4 [g_ * 512 + st + 256];  rw[3] = g_w4 [g_ * 512 + st + 384];   \
    rt[0] = g_kT4[g_ * 512 + st];        rt[1] = g_kT4[g_ * 512 + st + 128];   \
    rt[2] = g_kT4[g_ * 512 + st + 256];  rt[3] = g_kT4[g_ * 512 + st + 384];   \
    rl[0] = g_Lc4[g_ * 256 + st];        rl[1] = g_Lc4[g_ * 256 + st + 128];   \
    ru    = g_uB4[g_ * 512 + (size_t)sp * 128 + st];                           \
} while (0)

#define P2_STORES(BUF) do {                                                    \
    uint32_t bb = sb + (uint32_t)(BUF) * P2_BUF;                               \
    _Pragma("unroll")                                                          \
    for (int m = 0; m < 4; ++m) {                                              \
        int f = st + m * 128;                                                  \
        sts_v4(bb + P2_QD + (uint32_t)((f >> 4) * 272 + (f & 15) * 16), rq[m]);\
        sts_v4(bb + P2_WD + (uint32_t)((f >> 4) * 272 + (f & 15) * 16), rw[m]);\
        sts_v4(bb + P2_KT + (uint32_t)((f >> 3) * 144 + (f & 7)  * 16), rt[m]);\
    }                                                                          \
    _Pragma("unroll")                                                          \
    for (int m = 0; m < 2; ++m) {                                              \
        int f = st + m * 128;                                                  \
        sts_v4(bb + P2_LC + (uint32_t)((f >> 3) * 144 + (f & 7)  * 16), rl[m]);\
    }                                                                          \
    sts_v4(bb + P2_U0 + (uint32_t)((st >> 2) * 144 + (st & 3) * 16), ru);      \
} while (0)

        P2_LOADS(0);
        P2_STORES(0);
        P2_LOADS(1);
        __syncthreads();
        for (int t = 0; t < 256; ++t) {
            if (t + 1 < 256) P2_STORES((t + 1) & 1);   // regs loaded last iter
            if (t + 2 < 256) P2_LOADS(t + 2);          // full chunk to arrive
            __syncthreads();
        }
        return;
#undef P2_LOADS
#undef P2_STORES
    }

    // ====================== COMPUTE ROLE (warps 0-3) =========================
    const int c0 = sp * 16 + wp * 4;
    const uint32_t msb = sb + P2_MS + (uint32_t)wp * 1024;   // S mirror, col-major
    const uint32_t ulb = sb + P2_UL + (uint32_t)wp * 512;    // u local, col-major

#pragma unroll
    for (int c = 0; c < 4; ++c) {
        sts_f32(msb + (uint32_t)c * 256 + (uint32_t)lane * 4, 0.f);
        sts_f32(msb + (uint32_t)c * 256 + (uint32_t)(lane + 32) * 4, 0.f);
    }
    float S0[4] = {0.f, 0.f, 0.f, 0.f};   // S[lane][c]
    float S1[4] = {0.f, 0.f, 0.f, 0.f};   // S[lane+32][c]

    __syncthreads();   // matches staging warps' first barrier

    for (int t = 0; t < 256; ++t) {
        const uint32_t bb = sb + (uint32_t)(t & 1) * P2_BUF;

        // ---- u = u0 + (-w)@S ; o = q@S  (f32x2 over d-parity, 4 cols) -------
        const uint32_t wrow = bb + P2_WD + (uint32_t)lane * 272;
        const uint32_t qrow = bb + P2_QD + (uint32_t)lane * 272;
        u64 au[4] = {0, 0, 0, 0}, ao[4] = {0, 0, 0, 0};
#pragma unroll
        for (int i = 0; i < 16; ++i) {
            u64 w01, w23, q01, q23;
            ldsv2(w01, w23, wrow + (uint32_t)i * 16);
            ldsv2(q01, q23, qrow + (uint32_t)i * 16);
#pragma unroll
            for (int c = 0; c < 4; ++c) {
                u64 sa, sbv;
                ldsv2(sa, sbv, msb + (uint32_t)c * 256 + (uint32_t)i * 16);  // broadcast
                au[c] = fma2(w01, sa, au[c]);  au[c] = fma2(w23, sbv, au[c]);
                ao[c] = fma2(q01, sa, ao[c]);  ao[c] = fma2(q23, sbv, ao[c]);
            }
        }
        u64 ua, ub;
        ldsv2(ua, ub, bb + P2_U0 + (uint32_t)lane * 144 + (uint32_t)wp * 16);
        float2 u01 = unpack2(ua), u23 = unpack2(ub);
        float uu[4];
        uu[0] = u01.x + hadd2(au[0]);  uu[1] = u01.y + hadd2(au[1]);
        uu[2] = u23.x + hadd2(au[2]);  uu[3] = u23.y + hadd2(au[3]);

        // share u within warp via col-major smem (for broadcast j-pairs)
#pragma unroll
        for (int c = 0; c < 4; ++c)
            sts_f32(ulb + (uint32_t)c * 128 + (uint32_t)lane * 4, uu[c]);
        __syncwarp();

        // ---- o += Lc@u ; dS = k^T@u  (f32x2 over j-parity) -------------------
        const uint32_t lrow  = bb + P2_LC + (uint32_t)lane * 144;
        const uint32_t krow0 = bb + P2_KT + (uint32_t)lane * 144;
        const uint32_t krow1 = bb + P2_KT + (uint32_t)(lane + 32) * 144;
        u64 aoL[4] = {0, 0, 0, 0}, d0[4] = {0, 0, 0, 0}, d1[4] = {0, 0, 0, 0};
#pragma unroll
        for (int j4 = 0; j4 < 8; ++j4) {
            u64 L01, L23, k0a, k0b, k1a, k1b;
            ldsv2(L01, L23, lrow  + (uint32_t)j4 * 16);
            ldsv2(k0a, k0b, krow0 + (uint32_t)j4 * 16);
            ldsv2(k1a, k1b, krow1 + (uint32_t)j4 * 16);
#pragma unroll
            for (int c = 0; c < 4; ++c) {
                u64 up01, up23;
                ldsv2(up01, up23, ulb + (uint32_t)c * 128 + (uint32_t)j4 * 16);  // broadcast
                aoL[c] = fma2(L01, up01, aoL[c]);  aoL[c] = fma2(L23, up23, aoL[c]);
                d0[c]  = fma2(k0a, up01, d0[c]);   d0[c]  = fma2(k0b, up23, d0[c]);
                d1[c]  = fma2(k1a, up01, d1[c]);   d1[c]  = fma2(k1b, up23, d1[c]);
            }
        }

        float o[4];
#pragma unroll
        for (int c = 0; c < 4; ++c) {
            S0[c] += hadd2(d0[c]);
            S1[c] += hadd2(d1[c]);
            o[c] = hadd2(ao[c]) + hadd2(aoL[c]);
            sts_f32(msb + (uint32_t)c * 256 + (uint32_t)lane * 4, S0[c]);
            sts_f32(msb + (uint32_t)c * 256 + (uint32_t)(lane + 32) * 4, S1[c]);
        }

        size_t orow = ((size_t)bh * 8192 + (size_t)t * 32 + lane) * 64 + c0;
        *(float4*)(out + orow) = make_float4(o[0], o[1], o[2], o[3]);

        __syncthreads();   // next buffer staged; mirror writes visible in-warp
    }

    if (wantS) {
        size_t so = (size_t)O_ELEMS + (size_t)bh * 4096 + (size_t)lane * 64 + c0;
        *(float4*)(out + so)        = make_float4(S0[0], S0[1], S0[2], S0[3]);
        *(float4*)(out + so + 2048) = make_float4(S1[0], S1[1], S1[2], S1[3]);
    }
}

// ===========================================================================
extern "C" void kernel_launch(void* const* d_in, const int* in_sizes, int n_in,
                              void* d_out, int out_size)
{
    const float* q    = (const float*)d_in[0];
    const float* k    = (const float*)d_in[1];
    const float* v    = (const float*)d_in[2];
    const float* beta = (const float*)d_in[3];
    float* out = (float*)d_out;
    int wantS = (out_size > O_ELEMS) ? 1 : 0;

    cudaFuncSetAttribute(dn_phase2, cudaFuncAttributeMaxDynamicSharedMemorySize, P2_SMEM);

    dn_phase1<<<G_CHUNKS, 256>>>(q, k, v, beta);
    dn_phase2<<<128, 256, P2_SMEM>>>(out, wantS);
}